// round 2
// baseline (speedup 1.0000x reference)
#include <cuda_runtime.h>
#include <cuda_bf16.h>
#include <cstdint>

#define USER_NUM 100000
#define ITEM_NUM 50000
#define N_NODES  (USER_NUM + ITEM_NUM)   // 150000
#define EMB      64
#define TOT      (N_NODES * EMB)         // 9,600,000 floats
#define USER_ELEMS (USER_NUM * EMB)      // 6,400,000

// Ping-pong scratch (static device memory; no runtime allocation)
__device__ float g_bufA[TOT];
__device__ float g_bufB[TOT];

// ---------------------------------------------------------------------------
// init: acc(d_out) = ego, h(bufA) = ego, next(bufB) = 0.  float4 vectorized.
// USER_ELEMS is divisible by 4, so no float4 chunk straddles the boundary.
// ---------------------------------------------------------------------------
__global__ void init_kernel(const float4* __restrict__ user4,
                            const float4* __restrict__ item4,
                            float4* __restrict__ out4,
                            float4* __restrict__ hA4,
                            float4* __restrict__ hB4) {
    int i = blockIdx.x * blockDim.x + threadIdx.x;
    if (i >= TOT / 4) return;
    float4 v;
    if (i < USER_ELEMS / 4) v = user4[i];
    else                    v = item4[i - USER_ELEMS / 4];
    out4[i] = v;
    hA4[i]  = v;
    hB4[i]  = make_float4(0.f, 0.f, 0.f, 0.f);
}

// ---------------------------------------------------------------------------
// SpMM (COO scatter): y[row[e]] += vals[e] * x[col[e]]   over EMB=64 dims
// One warp processes 32 edges: coalesced per-lane edge loads, then shuffle-
// broadcast. Per edge, each lane handles a float2 (coalesced 256B gather) and
// issues a single red.global.add.v2.f32 (no-return vector reduction).
// Edge stream uses __ldcs (evict-first) so x/y stay L2-resident.
// ---------------------------------------------------------------------------
__global__ void spmm_kernel(const int*   __restrict__ row,
                            const int*   __restrict__ col,
                            const float* __restrict__ vals,
                            const float* __restrict__ x,
                            float*       __restrict__ y,
                            int nnz) {
    int gwarp = (blockIdx.x * blockDim.x + threadIdx.x) >> 5;
    int lane  = threadIdx.x & 31;
    int base  = gwarp * 32;
    if (base >= nnz) return;

    int   r = 0, c = 0;
    float v = 0.f;
    int e = base + lane;
    if (e < nnz) {
        r = __ldcs(row  + e);
        c = __ldcs(col  + e);
        v = __ldcs(vals + e);
    }
    int cnt = nnz - base;
    if (cnt > 32) cnt = 32;

    #pragma unroll 4
    for (int j = 0; j < cnt; j++) {
        int   rr = __shfl_sync(0xffffffffu, r, j);
        int   cc = __shfl_sync(0xffffffffu, c, j);
        float vv = __shfl_sync(0xffffffffu, v, j);

        const float2* xp = reinterpret_cast<const float2*>(x + (size_t)cc * EMB) + lane;
        float2 xv = __ldg(xp);
        float a = vv * xv.x;
        float b = vv * xv.y;

        float* dst = y + (size_t)rr * EMB + lane * 2;
        asm volatile("red.global.add.v2.f32 [%0], {%1, %2};"
                     :: "l"(dst), "f"(a), "f"(b) : "memory");
    }
}

// ---------------------------------------------------------------------------
// acc += src ; zero the next layer's output buffer
// ---------------------------------------------------------------------------
__global__ void add_zero_kernel(float4* __restrict__ acc4,
                                const float4* __restrict__ src4,
                                float4* __restrict__ zero4) {
    int i = blockIdx.x * blockDim.x + threadIdx.x;
    if (i >= TOT / 4) return;
    float4 a = acc4[i];
    float4 s = src4[i];
    a.x += s.x; a.y += s.y; a.z += s.z; a.w += s.w;
    acc4[i] = a;
    zero4[i] = make_float4(0.f, 0.f, 0.f, 0.f);
}

// ---------------------------------------------------------------------------
// acc = (acc + src) * 0.25  (final layer: fold in mean over 4 terms)
// ---------------------------------------------------------------------------
__global__ void add_scale_kernel(float4* __restrict__ acc4,
                                 const float4* __restrict__ src4) {
    int i = blockIdx.x * blockDim.x + threadIdx.x;
    if (i >= TOT / 4) return;
    float4 a = acc4[i];
    float4 s = src4[i];
    a.x = (a.x + s.x) * 0.25f;
    a.y = (a.y + s.y) * 0.25f;
    a.z = (a.z + s.z) * 0.25f;
    a.w = (a.w + s.w) * 0.25f;
    acc4[i] = a;
}

extern "C" void kernel_launch(void* const* d_in, const int* in_sizes, int n_in,
                              void* d_out, int out_size) {
    const float* user_emb = (const float*)d_in[0];
    const float* item_emb = (const float*)d_in[1];
    const int*   adj_row  = (const int*)  d_in[2];
    const int*   adj_col  = (const int*)  d_in[3];
    const float* adj_vals = (const float*)d_in[4];
    float* out = (float*)d_out;
    int nnz = in_sizes[2];

    float* bufA; cudaGetSymbolAddress((void**)&bufA, g_bufA);
    float* bufB; cudaGetSymbolAddress((void**)&bufB, g_bufB);

    const int EW_THREADS = 256;
    const int EW_BLOCKS  = (TOT / 4 + EW_THREADS - 1) / EW_THREADS;

    const int SP_THREADS = 256;                       // 8 warps / block
    int nwarps = (nnz + 31) / 32;
    int SP_BLOCKS = (nwarps + (SP_THREADS / 32) - 1) / (SP_THREADS / 32);

    // acc = ego ; h = ego (bufA) ; bufB = 0
    init_kernel<<<EW_BLOCKS, EW_THREADS>>>(
        (const float4*)user_emb, (const float4*)item_emb,
        (float4*)out, (float4*)bufA, (float4*)bufB);

    // layer 1: h1 = A*h0   (A reads bufA, writes bufB)
    spmm_kernel<<<SP_BLOCKS, SP_THREADS>>>(adj_row, adj_col, adj_vals, bufA, bufB, nnz);
    // acc += h1 ; zero bufA for next layer output
    add_zero_kernel<<<EW_BLOCKS, EW_THREADS>>>((float4*)out, (const float4*)bufB, (float4*)bufA);

    // layer 2: h2 = A*h1   (reads bufB, writes bufA)
    spmm_kernel<<<SP_BLOCKS, SP_THREADS>>>(adj_row, adj_col, adj_vals, bufB, bufA, nnz);
    // acc += h2 ; zero bufB for next layer output
    add_zero_kernel<<<EW_BLOCKS, EW_THREADS>>>((float4*)out, (const float4*)bufA, (float4*)bufB);

    // layer 3: h3 = A*h2   (reads bufA, writes bufB)
    spmm_kernel<<<SP_BLOCKS, SP_THREADS>>>(adj_row, adj_col, adj_vals, bufA, bufB, nnz);
    // acc = (acc + h3) / 4
    add_scale_kernel<<<EW_BLOCKS, EW_THREADS>>>((float4*)out, (const float4*)bufB);
}